// round 17
// baseline (speedup 1.0000x reference)
#include <cuda_runtime.h>

// RNN: B=4096, T=512, I=1, H=16, O=1
//   h_t = tanh(x_t*w_ih + b_ih + b_hh + W_hh h_{t-1}), h_0=0
//   out[b] = dot(h_T, w_fc) + b_fc
//
// R17: scalar-FFMA falsification test. Every structure using inline-asm
// f32x2 ops (64-bit "l" pair constraints) floors at C=170-185cy vs ~115
// modeled; suspect: ptxas MOV-pairs marshaling values into aligned
// register pairs around 20+ asm ops/step. This kernel is R14's exact
// structure with PURE SCALAR f32: scalar shuffles of h0/h1, scalar
// 4-accumulator FFMA trees, no packs, no asm in the loop except tanh.
// If C drops to ~140 the hypothesis is confirmed; if it stays ~175 the
// family floor is structural and R14 stands.
//
// Mapping: 8 lanes/element, lane m owns rows {2m, 2m+1}; 4 elements/warp;
// 1024 single-warp blocks; x staged in smem; tanh.approx.f32; shuffles
// issued in consumption order with late merge of the last-arriving value;
// seeds hoisted per 4-step block.

#define RNN_B 4096
#define RNN_T 512
#define RNN_H 16
#define XROW (RNN_T + 4)   // x row pad: groups' reads on distinct banks

__device__ __forceinline__ float tanh_approx(float x) {
    float y; asm("tanh.approx.f32 %0, %1;" : "=f"(y) : "f"(x)); return y;
}

__global__ __launch_bounds__(32) void rnn_scan_kernel(
    const float* __restrict__ x,      // [B, T, 1]
    const float* __restrict__ w_ih,   // [H]
    const float* __restrict__ w_hh,   // [H, H]
    const float* __restrict__ b_ih,   // [H]
    const float* __restrict__ b_hh,   // [H]
    const float* __restrict__ w_fc,   // [H]
    const float* __restrict__ b_fc,   // [1]
    float* __restrict__ out)          // [B]
{
    __shared__ __align__(16) float sx[4 * XROW];  // 4 sequences of x (~8.3KB)

    const int warp = blockIdx.x;      // one warp per block
    const int lane = threadIdx.x;     // 0..31
    const int g    = lane >> 3;       // element within warp (0..3)
    const int m    = lane & 7;        // lane within 8-lane group

    const int e  = warp * 4 + g;      // batch element, < 4096
    const int j0 = 2 * m;             // first owned row
    const int j1 = 2 * m + 1;         // second owned row

    // ---- Preload this warp's 4 contiguous x sequences (8KB) into smem. ----
    {
        const float4* src = reinterpret_cast<const float4*>(x + (long)warp * 4 * RNN_T);
        #pragma unroll
        for (int i = 0; i < 16; i++) {
            const int idx = i * 32 + lane;        // float4 index 0..511
            const float4 v = src[idx];
            const int f   = idx * 4;
            const int row = f >> 9;               // /512
            const int col = f & 511;
            *reinterpret_cast<float4*>(&sx[row * XROW + col]) = v;
        }
    }
    __syncwarp();

    // Scalar weights for both owned rows (32 registers).
    float w0[RNN_H], w1[RNN_H];
    {
        const float4* wa = reinterpret_cast<const float4*>(w_hh + j0 * RNN_H);
        const float4* wb = reinterpret_cast<const float4*>(w_hh + j1 * RNN_H);
        #pragma unroll
        for (int q = 0; q < 4; q++) {
            float4 ra = wa[q], rb = wb[q];
            w0[q*4+0] = ra.x; w0[q*4+1] = ra.y; w0[q*4+2] = ra.z; w0[q*4+3] = ra.w;
            w1[q*4+0] = rb.x; w1[q*4+1] = rb.y; w1[q*4+2] = rb.z; w1[q*4+3] = rb.w;
        }
    }
    const float wih0  = w_ih[j0];
    const float wih1  = w_ih[j1];
    const float bias0 = b_ih[j0] + b_hh[j0];
    const float bias1 = b_ih[j1] + b_hh[j1];

    const float4* sx4 = reinterpret_cast<const float4*>(&sx[g * XROW]);

    float h0 = 0.0f, h1 = 0.0f;       // owned hidden units (scalars)

    #pragma unroll 1
    for (int t4 = 0; t4 < RNN_T / 4; t4++) {
        const float4 xv = sx4[t4];    // broadcast LDS.128 within each group
        const float xs[4] = {xv.x, xv.y, xv.z, xv.w};

        // Hoisted seeds for all 4 substeps (pure f(x), off the h-chain).
        float sd0[4], sd1[4];
        #pragma unroll
        for (int s = 0; s < 4; s++) {
            sd0[s] = fmaf(xs[s], wih0, bias0);
            sd1[s] = fmaf(xs[s], wih1, bias1);
        }

        #pragma unroll
        for (int s = 0; s < 4; s++) {
            // Scalar gather, consumption-ordered: rv[2k]=h0@k, rv[2k+1]=h1@k.
            float rv[RNN_H];
            #pragma unroll
            for (int k = 0; k < 8; k++) {
                rv[2*k]   = __shfl_sync(0xffffffffu, h0, k, 8);
                rv[2*k+1] = __shfl_sync(0xffffffffu, h1, k, 8);
            }

            // Row j0: 4 accumulators, seeded, late merge on rv[15].
            float a0 = fmaf(w0[0], rv[0], sd0[s]);
            float a1 = w0[1] * rv[1];
            float a2 = w0[2] * rv[2];
            float a3 = w0[3] * rv[3];
            // Row j1: independent tree.
            float b0 = fmaf(w1[0], rv[0], sd1[s]);
            float b1 = w1[1] * rv[1];
            float b2 = w1[2] * rv[2];
            float b3 = w1[3] * rv[3];
            #pragma unroll
            for (int k = 4; k < 12; k += 4) {
                a0 = fmaf(w0[k+0], rv[k+0], a0);
                a1 = fmaf(w0[k+1], rv[k+1], a1);
                a2 = fmaf(w0[k+2], rv[k+2], a2);
                a3 = fmaf(w0[k+3], rv[k+3], a3);
                b0 = fmaf(w1[k+0], rv[k+0], b0);
                b1 = fmaf(w1[k+1], rv[k+1], b1);
                b2 = fmaf(w1[k+2], rv[k+2], b2);
                b3 = fmaf(w1[k+3], rv[k+3], b3);
            }
            a0 = fmaf(w0[12], rv[12], a0);
            a1 = fmaf(w0[13], rv[13], a1);
            a2 = fmaf(w0[14], rv[14], a2);
            b0 = fmaf(w1[12], rv[12], b0);
            b1 = fmaf(w1[13], rv[13], b1);
            b2 = fmaf(w1[14], rv[14], b2);
            // Merge first 15 terms while rv[15] is in flight; late merge.
            const float pA = (a0 + a1) + (a2 + a3);
            const float pB = (b0 + b1) + (b2 + b3);
            h0 = tanh_approx(fmaf(w0[15], rv[15], pA));
            h1 = tanh_approx(fmaf(w1[15], rv[15], pB));
        }
    }

    // out[e] = sum_j h[j]*w_fc[j] + b_fc  (reduce over the 8-lane group)
    float v = h0 * w_fc[j0] + h1 * w_fc[j1];
    #pragma unroll
    for (int off = 4; off; off >>= 1)
        v += __shfl_xor_sync(0xffffffffu, v, off, 8);
    if (m == 0)
        out[e] = v + b_fc[0];
}

extern "C" void kernel_launch(void* const* d_in, const int* in_sizes, int n_in,
                              void* d_out, int out_size) {
    const float* x    = (const float*)d_in[0];
    const float* w_ih = (const float*)d_in[1];
    const float* w_hh = (const float*)d_in[2];
    const float* b_ih = (const float*)d_in[3];
    const float* b_hh = (const float*)d_in[4];
    const float* w_fc = (const float*)d_in[5];
    const float* b_fc = (const float*)d_in[6];
    float* out = (float*)d_out;

    // 1024 single-warp blocks; 4 batch elements per warp, 8 lanes each.
    rnn_scan_kernel<<<RNN_B / 4, 32>>>(x, w_ih, w_hh, b_ih, b_hh, w_fc, b_fc, out);
}